// round 16
// baseline (speedup 1.0000x reference)
#include <cuda_runtime.h>
#include <cuda_fp16.h>
#include <cstdint>

typedef unsigned long long ull;

#define N_NODES 21
#define N_EDGES 23
#define D1 64
#define D2 128
#define G_TOTAL 32768
#define WPB 8
#define BLOCK 256
#define GB 16               // graphs per warp
#define M_TILE 128          // graphs per CTA
#define PADK 136
#define RSTRIDE (PADK * 2)  // 272 bytes (row capacity; fp16 uses first 128 B)

// ---- shared layout (float indices) ----
#define OFF_C2   0           // float2 (c/2,c/2) x21, pad 48
#define OFF_D2   48          // float2 (d,d) x21, pad 48
#define OFF_SC   96          // sum(c/2), pad to 112
#define OFF_TW   112         // [21][3]
#define OFF_TI   176         // [21][3]
#define OFF_B2   240         // b2 -> 368
#define OFF_Z    368         // 8 warps x 16 float2 -> 624
#define OFF_Y    624         // y4 dup: 8 warps x 16*21 float4 = 10752 floats -> 11376
#define OFF_A    11376       // A tile 128x136 rows (fp16 data in first 128 B/row); byte 45504, 16B ok
#define OFF_B    (OFF_A + 8704)         // B tile
#define SMEM_FLOATS (OFF_B + 8704)      // 28784
#define SMEM_BYTES  (SMEM_FLOATS * 4)   // 115136  (2 CTAs x 115136 = 230272 <= 233472)

__device__ __forceinline__ ull ffma2(ull a, ull b, ull c) {
    ull d; asm("fma.rn.f32x2 %0, %1, %2, %3;" : "=l"(d) : "l"(a), "l"(b), "l"(c)); return d;
}
__device__ __forceinline__ ull addf2(ull a, ull b) {
    ull d; asm("add.rn.f32x2 %0, %1, %2;" : "=l"(d) : "l"(a), "l"(b)); return d;
}
__device__ __forceinline__ ull pack2(float lo, float hi) {
    ull d; asm("mov.b64 %0, {%1, %2};" : "=l"(d) : "f"(lo), "f"(hi)); return d;
}
__device__ __forceinline__ void unpack2(ull v, float& lo, float& hi) {
    asm("mov.b64 {%0, %1}, %2;" : "=f"(lo), "=f"(hi) : "l"(v));
}
// packed half2: low half = l, high half = h
__device__ __forceinline__ uint32_t cvt_f16x2(float h, float l) {
    uint32_t r; asm("cvt.rn.f16x2.f32 %0, %1, %2;" : "=r"(r) : "f"(h), "f"(l)); return r;
}
__device__ __forceinline__ uint32_t smem_u32(const void* p) {
    uint32_t a; asm("{ .reg .u64 t; cvta.to.shared.u64 t, %1; cvt.u32.u64 %0, t; }" : "=r"(a) : "l"(p));
    return a;
}
__device__ __forceinline__ void mma_f16(float& c0, float& c1, float& c2, float& c3,
                                        uint32_t a0, uint32_t a1, uint32_t a2, uint32_t a3,
                                        uint32_t b0, uint32_t b1) {
    asm("mma.sync.aligned.m16n8k16.row.col.f32.f16.f16.f32 "
        "{%0,%1,%2,%3}, {%4,%5,%6,%7}, {%8,%9}, {%0,%1,%2,%3};"
        : "+f"(c0), "+f"(c1), "+f"(c2), "+f"(c3)
        : "r"(a0), "r"(a1), "r"(a2), "r"(a3), "r"(b0), "r"(b1));
}
__device__ __forceinline__ void ldm_x4(uint32_t& r0, uint32_t& r1, uint32_t& r2, uint32_t& r3,
                                       uint32_t addr) {
    asm volatile("ldmatrix.sync.aligned.m8n8.x4.shared.b16 {%0,%1,%2,%3}, [%4];"
        : "=r"(r0), "=r"(r1), "=r"(r2), "=r"(r3) : "r"(addr));
}

__device__ __constant__ signed char c_esrc[N_EDGES] =
    {0,1,2,3, 0,5,6,7, 0,9,10,11, 0,13,14,15, 0,17,18,19, 5,9,13};
__device__ __constant__ signed char c_etgt[N_EDGES] =
    {1,2,3,4, 5,6,7,8, 9,10,11,12, 13,14,15,16, 17,18,19,20, 9,13,17};
#define R2C 0.70710678118654752f
#define R3C 0.57735026918962576f
__device__ __constant__ float c_dis[N_NODES] = {
    1.0f, R2C, R2C, R2C, R2C,  R2C, R2C, R2C, R2C,
    R3C, R2C, R2C, R2C,  R3C, R2C, R2C, R2C,  R3C, R2C, R2C, R2C
};

__global__ void __launch_bounds__(BLOCK, 2)
hand_gnn_kernel(const float* __restrict__ x,
                const float* __restrict__ W1,
                const float* __restrict__ b1,
                const float* __restrict__ W2,
                const float* __restrict__ b2,
                float* __restrict__ out)
{
    extern __shared__ float sm[];
    char* smc = (char*)sm;
    const int tid  = threadIdx.x;
    const int w    = tid >> 5;
    const int lane = tid & 31;

    // ---- W2 prefetch (registers; dead before phase 1) ----
    float4 rw0[4], rw1[4];
    #pragma unroll
    for (int it = 0; it < 4; it++) {
        const int idx = tid + it * BLOCK;
        const int fp  = idx >> 5;
        const int nb  = idx & 31;
        rw0[it] = *(const float4*)(W2 + (2*fp)     * D2 + 4*nb);
        rw1[it] = *(const float4*)(W2 + (2*fp + 1) * D2 + 4*nb);
    }

    // ---- prolog pass 1: tables, c/2, b2 ----
    if (tid < D2) sm[OFF_B2 + tid] = b2[tid];
    if (tid < N_NODES) {
        const int t = tid;
        const float dt = c_dis[t];
        float* sTw = sm + OFF_TW;  int* sTi = (int*)(sm + OFF_TI);
        sTw[t*3+0] = dt*dt;  sTi[t*3+0] = t;
        int p = 1;
        #pragma unroll
        for (int e = 0; e < N_EDGES; e++)
            if ((int)c_etgt[e] == t) { sTw[t*3+p] = dt*c_dis[(int)c_esrc[e]]; sTi[t*3+p] = (int)c_esrc[e]; p++; }
        for (; p < 3; p++) { sTw[t*3+p] = 0.0f; sTi[t*3+p] = 0; }
        float cs = dt;
        #pragma unroll
        for (int e = 0; e < N_EDGES; e++)
            if ((int)c_esrc[e] == t) cs += c_dis[(int)c_etgt[e]];
        float ch = dt * cs * (1.0f / 42.0f);          // c_t/2
        ((float2*)(sm + OFF_C2))[t] = make_float2(ch, ch);
    }
    __syncthreads();

    // ---- prolog pass 2: d = A^T(c/2), sc; B tile (fp16) from prefetched regs ----
    if (tid < N_NODES) {
        const int s = tid;
        const float ds = c_dis[s];
        float acc = ds * ((const float2*)(sm + OFF_C2))[s].x;
        #pragma unroll
        for (int e = 0; e < N_EDGES; e++)
            if ((int)c_esrc[e] == s)
                acc += c_dis[(int)c_etgt[e]] * ((const float2*)(sm + OFF_C2))[(int)c_etgt[e]].x;
        float d = ds * acc;
        ((float2*)(sm + OFF_D2))[s] = make_float2(d, d);
    }
    if (tid == 0) {
        float sc = 0.0f;
        #pragma unroll
        for (int t = 0; t < N_NODES; t++) sc += ((const float2*)(sm + OFF_C2))[t].x;
        sm[OFF_SC] = sc;
    }
    {   // B[n][k] fp16 (k = 0..63), n-major, 272-B padded rows
        char* B = smc + OFF_B * 4;
        #pragma unroll
        for (int it = 0; it < 4; it++) {
            const int idx = tid + it * BLOCK;
            const int fp  = idx >> 5;
            const int nb  = idx & 31;
            const float e0[4] = {rw0[it].x, rw0[it].y, rw0[it].z, rw0[it].w};
            const float e1[4] = {rw1[it].x, rw1[it].y, rw1[it].z, rw1[it].w};
            #pragma unroll
            for (int nn = 0; nn < 4; nn++) {
                const int n = 4*nb + nn;
                // low half = W2[2fp][n] (k even), high = W2[2fp+1][n]
                *(uint32_t*)(B + n * RSTRIDE + 4 * fp) = cvt_f16x2(e1[nn], e0[nn]);
            }
        }
    }
    __syncthreads();   // LAST block-wide barrier

    // ================= free-flowing per-warp body (no __syncthreads) =============
    const int g_base = blockIdx.x * M_TILE;
    const int g0w    = g_base + w * GB;

    // x staging: inside this warp's OWN A rows (16 * 272 B = 4352 B >= 2688 B)
    float*  sx  = sm + OFF_A + w * (GB * PADK / 2);   // w * 1088 floats
    float4* sy4 = (float4*)(sm + OFF_Y) + w * (GB * N_NODES);
    float2* sz  = (float2*)(sm + OFF_Z) + w * GB;

    {   // coalesced x load: 672 floats / warp
        const float4* xg = (const float4*)(x + (size_t)g0w * N_NODES * 2);
        float4* d = (float4*)sx;
        #pragma unroll
        for (int i = lane; i < 672 / 4; i += 32) d[i] = xg[i];
    }
    __syncwarp();

    if (lane < N_NODES) {   // sparse y = A @ x, stored pre-duplicated (y0,y0,y1,y1)
        const float* sTw = sm + OFF_TW;  const int* sTi = (const int*)(sm + OFF_TI);
        const float tw0 = sTw[lane*3+0]; const int ti0 = sTi[lane*3+0];
        const float tw1 = sTw[lane*3+1]; const int ti1 = sTi[lane*3+1];
        const float tw2 = sTw[lane*3+2]; const int ti2 = sTi[lane*3+2];
        #pragma unroll 4
        for (int j = 0; j < GB; j++) {
            const float2* xj = (const float2*)(sx + j * N_NODES * 2);
            ull y2;
            y2 = ffma2(pack2(tw0, tw0), *(const ull*)&xj[ti0], 0ull);
            y2 = ffma2(pack2(tw1, tw1), *(const ull*)&xj[ti1], y2);
            y2 = ffma2(pack2(tw2, tw2), *(const ull*)&xj[ti2], y2);
            float y0, y1; unpack2(y2, y0, y1);
            sy4[j * N_NODES + lane] = make_float4(y0, y0, y1, y1);
        }
    }
    if (lane < GB) {        // z[j] = d^T x_j
        const ull* xj = (const ull*)(sx + lane * N_NODES * 2);
        const ull* dD = (const ull*)(sm + OFF_D2);
        ull z2 = 0;
        #pragma unroll
        for (int s = 0; s < N_NODES; s++) z2 = ffma2(dD[s], xj[s], z2);
        *(ull*)&sz[lane] = z2;
    }
    __syncwarp();

    const ull W10p = pack2(W1[2*lane],      W1[2*lane + 1]);
    const ull W11p = pack2(W1[D1 + 2*lane], W1[D1 + 2*lane + 1]);
    const ull B1p  = pack2(b1[2*lane],      b1[2*lane + 1]);
    const float scv = sm[OFF_SC];
    const ull SCB1p = pack2(scv * b1[2*lane], scv * b1[2*lane + 1]);
    const ull ABSM = 0x7FFFFFFF7FFFFFFFull;

    // vA[j] = sum_t (c_t/2)|h_t|   — 5 ops/iter (LDS.128 + 2 FFMA2 + AND + FFMA2)
    ull vA[GB];
    #pragma unroll
    for (int j = 0; j < GB; j++) vA[j] = 0ull;
    for (int t = 0; t < N_NODES; t++) {
        const ull c2 = ((const ull*)(sm + OFF_C2))[t];
        #pragma unroll
        for (int j = 0; j < GB; j++) {
            float4 yd = sy4[j * N_NODES + t];     // LDS.128 broadcast
            ull y0 = *(const ull*)&yd.x;          // (y0,y0)
            ull y1 = *(const ull*)&yd.z;          // (y1,y1)
            ull h  = ffma2(y0, W10p, ffma2(y1, W11p, B1p));
            vA[j]  = ffma2(c2, h & ABSM, vA[j]);
        }
    }
    __syncwarp();   // x staging (in own A rows) fully consumed

    // ---- finalize v, write OWN A rows (fp16, cols 2l,2l+1) ----
    {
        char* A = smc + OFF_A * 4;
        #pragma unroll 4
        for (int j = 0; j < GB; j++) {
            const int row = w * GB + j;
            float2 zj = sz[j];
            ull lin = ffma2(pack2(zj.x, zj.x), W10p,
                      ffma2(pack2(zj.y, zj.y), W11p, SCB1p));
            ull v = addf2(lin, vA[j]);
            float va, vb; unpack2(v, va, vb);     // features 2l, 2l+1
            *(uint32_t*)(A + row * RSTRIDE + 4 * lane) = cvt_f16x2(vb, va);
        }
    }
    __syncwarp();   // own A rows visible to own ldmatrix

    // ---- epilogue: out[16x128] = V(fp16) x W(fp16) + b2 ----
    const int r  = lane >> 2;
    const int tq = (lane & 3) * 2;

    float c[16][4];
    #pragma unroll
    for (int m = 0; m < 16; m++) {
        float2 bb = *(const float2*)(sm + OFF_B2 + m * 8 + tq);
        c[m][0] = bb.x;  c[m][1] = bb.y;  c[m][2] = bb.x;  c[m][3] = bb.y;
    }

    const uint32_t smb = smem_u32(sm);
    const int tile = lane >> 3, lr = lane & 7;
    const uint32_t aBase = smb + OFF_A * 4
        + (uint32_t)((w * GB + (tile & 1) * 8 + lr) * RSTRIDE + (tile >> 1) * 16);
    const uint32_t bBase = smb + OFF_B * 4
        + (uint32_t)(((tile & 1) * 8 + lr) * RSTRIDE + (tile >> 1) * 16);

    #pragma unroll
    for (int ks = 0; ks < 4; ks++) {
        const int ka = ks * 16;
        uint32_t a0, a1, a2, a3;
        ldm_x4(a0, a1, a2, a3, aBase + ka * 2);
        #pragma unroll
        for (int mp = 0; mp < 8; mp++) {
            uint32_t h0, h1, h2, h3;
            ldm_x4(h0, h1, h2, h3, bBase + (uint32_t)(mp * 16 * RSTRIDE + ka * 2));
            mma_f16(c[2*mp][0],   c[2*mp][1],   c[2*mp][2],   c[2*mp][3],
                    a0, a1, a2, a3, h0, h2);
            mma_f16(c[2*mp+1][0], c[2*mp+1][1], c[2*mp+1][2], c[2*mp+1][3],
                    a0, a1, a2, a3, h1, h3);
        }
    }

    // ---- store ----
    {
        float* o0 = out + (size_t)(g0w + r) * D2;
        float* o1 = o0 + 8 * D2;
        #pragma unroll
        for (int m = 0; m < 16; m++) {
            *(float2*)(o0 + m * 8 + tq) = make_float2(c[m][0], c[m][1]);
            *(float2*)(o1 + m * 8 + tq) = make_float2(c[m][2], c[m][3]);
        }
    }
}

extern "C" void kernel_launch(void* const* d_in, const int* in_sizes, int n_in,
                              void* d_out, int out_size) {
    const float* x  = (const float*)d_in[0];
    const float* W1 = (const float*)d_in[1];
    const float* b1 = (const float*)d_in[2];
    const float* W2 = (const float*)d_in[3];
    const float* b2 = (const float*)d_in[4];
    float* out = (float*)d_out;

    cudaFuncSetAttribute(hand_gnn_kernel,
                         cudaFuncAttributeMaxDynamicSharedMemorySize, SMEM_BYTES);
    hand_gnn_kernel<<<G_TOTAL / M_TILE, BLOCK, SMEM_BYTES>>>(x, W1, b1, W2, b2, out);
}

// round 17
// speedup vs baseline: 1.0890x; 1.0890x over previous
#include <cuda_runtime.h>
#include <cuda_fp16.h>
#include <cstdint>

typedef unsigned long long ull;

#define N_NODES 21
#define N_EDGES 23
#define D1 64
#define D2 128
#define G_TOTAL 32768
#define WPB 8
#define BLOCK 256
#define GB 16               // graphs per warp
#define M_TILE 128          // graphs per CTA
#define PADK 136
#define RSTRIDE (PADK * 2)  // 272 bytes (row capacity; fp16 uses first 128 B)
#define YSTRIDE 22          // padded y stride (float2 per graph) -> 16B-aligned t-pairs

// ---- shared layout (float indices) ----
#define OFF_C2   0           // float2 (c/2,c/2) x21, pad 48
#define OFF_D2   48          // float2 (d,d) x21, pad 48
#define OFF_SC   96          // sum(c/2), pad to 112
#define OFF_TW   112         // [21][3]
#define OFF_TI   176         // [21][3]
#define OFF_B2   240         // b2 -> 368
#define OFF_Z    368         // 8 warps x 16 float2 -> 624
#define OFF_Y    624         // y2: 8 warps x 16*22 float2 = 5632 floats -> 6256
#define OFF_A    6256        // A tile 128x136 rows (fp16 in first 128 B/row); byte 25024, 16B ok
#define OFF_B    (OFF_A + 8704)         // B tile
#define SMEM_FLOATS (OFF_B + 8704)      // 23664
#define SMEM_BYTES  (SMEM_FLOATS * 4)   // 94656  (2 x 94656 = 189312 <= 233472)

__device__ __forceinline__ ull ffma2(ull a, ull b, ull c) {
    ull d; asm("fma.rn.f32x2 %0, %1, %2, %3;" : "=l"(d) : "l"(a), "l"(b), "l"(c)); return d;
}
__device__ __forceinline__ ull addf2(ull a, ull b) {
    ull d; asm("add.rn.f32x2 %0, %1, %2;" : "=l"(d) : "l"(a), "l"(b)); return d;
}
__device__ __forceinline__ ull pack2(float lo, float hi) {
    ull d; asm("mov.b64 %0, {%1, %2};" : "=l"(d) : "f"(lo), "f"(hi)); return d;
}
__device__ __forceinline__ void unpack2(ull v, float& lo, float& hi) {
    asm("mov.b64 {%0, %1}, %2;" : "=f"(lo), "=f"(hi) : "l"(v));
}
// packed half2: low half = l, high half = h
__device__ __forceinline__ uint32_t cvt_f16x2(float h, float l) {
    uint32_t r; asm("cvt.rn.f16x2.f32 %0, %1, %2;" : "=r"(r) : "f"(h), "f"(l)); return r;
}
__device__ __forceinline__ uint32_t smem_u32(const void* p) {
    uint32_t a; asm("{ .reg .u64 t; cvta.to.shared.u64 t, %1; cvt.u32.u64 %0, t; }" : "=r"(a) : "l"(p));
    return a;
}
__device__ __forceinline__ void mma_f16(float& c0, float& c1, float& c2, float& c3,
                                        uint32_t a0, uint32_t a1, uint32_t a2, uint32_t a3,
                                        uint32_t b0, uint32_t b1) {
    asm("mma.sync.aligned.m16n8k16.row.col.f32.f16.f16.f32 "
        "{%0,%1,%2,%3}, {%4,%5,%6,%7}, {%8,%9}, {%0,%1,%2,%3};"
        : "+f"(c0), "+f"(c1), "+f"(c2), "+f"(c3)
        : "r"(a0), "r"(a1), "r"(a2), "r"(a3), "r"(b0), "r"(b1));
}
__device__ __forceinline__ void ldm_x4(uint32_t& r0, uint32_t& r1, uint32_t& r2, uint32_t& r3,
                                       uint32_t addr) {
    asm volatile("ldmatrix.sync.aligned.m8n8.x4.shared.b16 {%0,%1,%2,%3}, [%4];"
        : "=r"(r0), "=r"(r1), "=r"(r2), "=r"(r3) : "r"(addr));
}

__device__ __constant__ signed char c_esrc[N_EDGES] =
    {0,1,2,3, 0,5,6,7, 0,9,10,11, 0,13,14,15, 0,17,18,19, 5,9,13};
__device__ __constant__ signed char c_etgt[N_EDGES] =
    {1,2,3,4, 5,6,7,8, 9,10,11,12, 13,14,15,16, 17,18,19,20, 9,13,17};
#define R2C 0.70710678118654752f
#define R3C 0.57735026918962576f
__device__ __constant__ float c_dis[N_NODES] = {
    1.0f, R2C, R2C, R2C, R2C,  R2C, R2C, R2C, R2C,
    R3C, R2C, R2C, R2C,  R3C, R2C, R2C, R2C,  R3C, R2C, R2C, R2C
};

__global__ void __launch_bounds__(BLOCK, 2)
hand_gnn_kernel(const float* __restrict__ x,
                const float* __restrict__ W1,
                const float* __restrict__ b1,
                const float* __restrict__ W2,
                const float* __restrict__ b2,
                float* __restrict__ out)
{
    extern __shared__ float sm[];
    char* smc = (char*)sm;
    const int tid  = threadIdx.x;
    const int w    = tid >> 5;
    const int lane = tid & 31;

    // ---- W2 prefetch (registers; dead before phase 1) ----
    float4 rw0[4], rw1[4];
    #pragma unroll
    for (int it = 0; it < 4; it++) {
        const int idx = tid + it * BLOCK;
        const int fp  = idx >> 5;
        const int nb  = idx & 31;
        rw0[it] = *(const float4*)(W2 + (2*fp)     * D2 + 4*nb);
        rw1[it] = *(const float4*)(W2 + (2*fp + 1) * D2 + 4*nb);
    }

    // ---- prolog pass 1: tables, c/2, b2 ----
    if (tid < D2) sm[OFF_B2 + tid] = b2[tid];
    if (tid < N_NODES) {
        const int t = tid;
        const float dt = c_dis[t];
        float* sTw = sm + OFF_TW;  int* sTi = (int*)(sm + OFF_TI);
        sTw[t*3+0] = dt*dt;  sTi[t*3+0] = t;
        int p = 1;
        #pragma unroll
        for (int e = 0; e < N_EDGES; e++)
            if ((int)c_etgt[e] == t) { sTw[t*3+p] = dt*c_dis[(int)c_esrc[e]]; sTi[t*3+p] = (int)c_esrc[e]; p++; }
        for (; p < 3; p++) { sTw[t*3+p] = 0.0f; sTi[t*3+p] = 0; }
        float cs = dt;
        #pragma unroll
        for (int e = 0; e < N_EDGES; e++)
            if ((int)c_esrc[e] == t) cs += c_dis[(int)c_etgt[e]];
        float ch = dt * cs * (1.0f / 42.0f);          // c_t/2
        ((float2*)(sm + OFF_C2))[t] = make_float2(ch, ch);
    }
    __syncthreads();

    // ---- prolog pass 2: d = A^T(c/2), sc; B tile (fp16) from prefetched regs ----
    if (tid < N_NODES) {
        const int s = tid;
        const float ds = c_dis[s];
        float acc = ds * ((const float2*)(sm + OFF_C2))[s].x;
        #pragma unroll
        for (int e = 0; e < N_EDGES; e++)
            if ((int)c_esrc[e] == s)
                acc += c_dis[(int)c_etgt[e]] * ((const float2*)(sm + OFF_C2))[(int)c_etgt[e]].x;
        float d = ds * acc;
        ((float2*)(sm + OFF_D2))[s] = make_float2(d, d);
    }
    if (tid == 0) {
        float sc = 0.0f;
        #pragma unroll
        for (int t = 0; t < N_NODES; t++) sc += ((const float2*)(sm + OFF_C2))[t].x;
        sm[OFF_SC] = sc;
    }
    {   // B[n][k] fp16 (k = 0..63), n-major, 272-B padded rows
        char* B = smc + OFF_B * 4;
        #pragma unroll
        for (int it = 0; it < 4; it++) {
            const int idx = tid + it * BLOCK;
            const int fp  = idx >> 5;
            const int nb  = idx & 31;
            const float e0[4] = {rw0[it].x, rw0[it].y, rw0[it].z, rw0[it].w};
            const float e1[4] = {rw1[it].x, rw1[it].y, rw1[it].z, rw1[it].w};
            #pragma unroll
            for (int nn = 0; nn < 4; nn++) {
                const int n = 4*nb + nn;
                // low half = W2[2fp][n] (k even), high = W2[2fp+1][n]
                *(uint32_t*)(B + n * RSTRIDE + 4 * fp) = cvt_f16x2(e1[nn], e0[nn]);
            }
        }
    }
    __syncthreads();   // LAST block-wide barrier

    // ================= free-flowing per-warp body (no __syncthreads) =============
    const int g_base = blockIdx.x * M_TILE;
    const int g0w    = g_base + w * GB;

    // x staging: inside this warp's OWN A rows (16 * 272 B = 4352 B >= 2688 B)
    float*  sx  = sm + OFF_A + w * (GB * PADK / 2);   // w * 1088 floats
    float2* sy2 = (float2*)(sm + OFF_Y) + w * (GB * YSTRIDE);
    float2* sz  = (float2*)(sm + OFF_Z) + w * GB;

    {   // coalesced x load: 672 floats / warp
        const float4* xg = (const float4*)(x + (size_t)g0w * N_NODES * 2);
        float4* d = (float4*)sx;
        #pragma unroll
        for (int i = lane; i < 672 / 4; i += 32) d[i] = xg[i];
    }
    __syncwarp();

    if (lane < N_NODES) {   // sparse y = A @ x (compact, stride-22 rows)
        const float* sTw = sm + OFF_TW;  const int* sTi = (const int*)(sm + OFF_TI);
        const float tw0 = sTw[lane*3+0]; const int ti0 = sTi[lane*3+0];
        const float tw1 = sTw[lane*3+1]; const int ti1 = sTi[lane*3+1];
        const float tw2 = sTw[lane*3+2]; const int ti2 = sTi[lane*3+2];
        #pragma unroll 4
        for (int j = 0; j < GB; j++) {
            const float2* xj = (const float2*)(sx + j * N_NODES * 2);
            ull y2;
            y2 = ffma2(pack2(tw0, tw0), *(const ull*)&xj[ti0], 0ull);
            y2 = ffma2(pack2(tw1, tw1), *(const ull*)&xj[ti1], y2);
            y2 = ffma2(pack2(tw2, tw2), *(const ull*)&xj[ti2], y2);
            *(ull*)&sy2[j * YSTRIDE + lane] = y2;
        }
    }
    if (lane < GB) {        // z[j] = d^T x_j
        const ull* xj = (const ull*)(sx + lane * N_NODES * 2);
        const ull* dD = (const ull*)(sm + OFF_D2);
        ull z2 = 0;
        #pragma unroll
        for (int s = 0; s < N_NODES; s++) z2 = ffma2(dD[s], xj[s], z2);
        *(ull*)&sz[lane] = z2;
    }
    __syncwarp();

    const ull W10p = pack2(W1[2*lane],      W1[2*lane + 1]);
    const ull W11p = pack2(W1[D1 + 2*lane], W1[D1 + 2*lane + 1]);
    const ull B1p  = pack2(b1[2*lane],      b1[2*lane + 1]);
    const float scv = sm[OFF_SC];
    const ull SCB1p = pack2(scv * b1[2*lane], scv * b1[2*lane + 1]);
    const ull ABSM = 0x7FFFFFFF7FFFFFFFull;

    // vA[j] = sum_t (c_t/2)|h_t| — t-paired: one LDS.128 serves nodes (t, t+1)
    ull vA[GB];
    #pragma unroll
    for (int j = 0; j < GB; j++) vA[j] = 0ull;
    for (int tp = 0; tp < 20; tp += 2) {
        const ull c2a = ((const ull*)(sm + OFF_C2))[tp];
        const ull c2b = ((const ull*)(sm + OFF_C2))[tp + 1];
        #pragma unroll
        for (int j = 0; j < GB; j++) {
            float4 yp = *(const float4*)&sy2[j * YSTRIDE + tp];  // (y0_t,y1_t,y0_t1,y1_t1)
            ull y0a = pack2(yp.x, yp.x);
            ull y1a = pack2(yp.y, yp.y);
            ull y0b = pack2(yp.z, yp.z);
            ull y1b = pack2(yp.w, yp.w);
            ull ha = ffma2(y0a, W10p, ffma2(y1a, W11p, B1p));
            ull hb = ffma2(y0b, W10p, ffma2(y1b, W11p, B1p));
            vA[j] = ffma2(c2a, ha & ABSM, vA[j]);
            vA[j] = ffma2(c2b, hb & ABSM, vA[j]);
        }
    }
    {   // tail t = 20
        const ull c2 = ((const ull*)(sm + OFF_C2))[20];
        #pragma unroll
        for (int j = 0; j < GB; j++) {
            float2 yt = sy2[j * YSTRIDE + 20];
            ull y0 = pack2(yt.x, yt.x);
            ull y1 = pack2(yt.y, yt.y);
            ull h  = ffma2(y0, W10p, ffma2(y1, W11p, B1p));
            vA[j]  = ffma2(c2, h & ABSM, vA[j]);
        }
    }
    __syncwarp();   // x staging (in own A rows) fully consumed

    // ---- finalize v, write OWN A rows (fp16, cols 2l,2l+1) ----
    {
        char* A = smc + OFF_A * 4;
        #pragma unroll 4
        for (int j = 0; j < GB; j++) {
            const int row = w * GB + j;
            float2 zj = sz[j];
            ull lin = ffma2(pack2(zj.x, zj.x), W10p,
                      ffma2(pack2(zj.y, zj.y), W11p, SCB1p));
            ull v = addf2(lin, vA[j]);
            float va, vb; unpack2(v, va, vb);     // features 2l, 2l+1
            *(uint32_t*)(A + row * RSTRIDE + 4 * lane) = cvt_f16x2(vb, va);
        }
    }
    __syncwarp();   // own A rows visible to own ldmatrix

    // ---- epilogue: out[16x128] = V(fp16) x W(fp16) + b2 ----
    const int r  = lane >> 2;
    const int tq = (lane & 3) * 2;

    float c[16][4];
    #pragma unroll
    for (int m = 0; m < 16; m++) {
        float2 bb = *(const float2*)(sm + OFF_B2 + m * 8 + tq);
        c[m][0] = bb.x;  c[m][1] = bb.y;  c[m][2] = bb.x;  c[m][3] = bb.y;
    }

    const uint32_t smb = smem_u32(sm);
    const int tile = lane >> 3, lr = lane & 7;
    const uint32_t aBase = smb + OFF_A * 4
        + (uint32_t)((w * GB + (tile & 1) * 8 + lr) * RSTRIDE + (tile >> 1) * 16);
    const uint32_t bBase = smb + OFF_B * 4
        + (uint32_t)(((tile & 1) * 8 + lr) * RSTRIDE + (tile >> 1) * 16);

    #pragma unroll
    for (int ks = 0; ks < 4; ks++) {
        const int ka = ks * 16;
        uint32_t a0, a1, a2, a3;
        ldm_x4(a0, a1, a2, a3, aBase + ka * 2);
        #pragma unroll
        for (int mp = 0; mp < 8; mp++) {
            uint32_t h0, h1, h2, h3;
            ldm_x4(h0, h1, h2, h3, bBase + (uint32_t)(mp * 16 * RSTRIDE + ka * 2));
            mma_f16(c[2*mp][0],   c[2*mp][1],   c[2*mp][2],   c[2*mp][3],
                    a0, a1, a2, a3, h0, h2);
            mma_f16(c[2*mp+1][0], c[2*mp+1][1], c[2*mp+1][2], c[2*mp+1][3],
                    a0, a1, a2, a3, h1, h3);
        }
    }

    // ---- store ----
    {
        float* o0 = out + (size_t)(g0w + r) * D2;
        float* o1 = o0 + 8 * D2;
        #pragma unroll
        for (int m = 0; m < 16; m++) {
            *(float2*)(o0 + m * 8 + tq) = make_float2(c[m][0], c[m][1]);
            *(float2*)(o1 + m * 8 + tq) = make_float2(c[m][2], c[m][3]);
        }
    }
}

extern "C" void kernel_launch(void* const* d_in, const int* in_sizes, int n_in,
                              void* d_out, int out_size) {
    const float* x  = (const float*)d_in[0];
    const float* W1 = (const float*)d_in[1];
    const float* b1 = (const float*)d_in[2];
    const float* W2 = (const float*)d_in[3];
    const float* b2 = (const float*)d_in[4];
    float* out = (float*)d_out;

    cudaFuncSetAttribute(hand_gnn_kernel,
                         cudaFuncAttributeMaxDynamicSharedMemorySize, SMEM_BYTES);
    hand_gnn_kernel<<<G_TOTAL / M_TILE, BLOCK, SMEM_BYTES>>>(x, W1, b1, W2, b2, out);
}